// round 14
// baseline (speedup 1.0000x reference)
#include <cuda_runtime.h>
#include <cstdint>

#define NUM_CLASSES 7
#define NTHREADS 256
#define ROWS_TILE 512                  // rows per tile (multiple of 4)
#define LOG_BYTES (ROWS_TILE * 28)     // 14336: logits only in SMEM
#define NSTAGES 4
#define SMEM_DYN (NSTAGES * LOG_BYTES) // 57344 B -> 3 blocks/SM
#define NBLOCKS 444                    // 148 SMs * 3 resident

__device__ double g_sum = 0.0;
__device__ unsigned int g_done_count = 0;
__device__ unsigned int g_tile = 0;

__device__ __forceinline__ uint32_t smem_u32(const void* p) {
    uint32_t a;
    asm("{ .reg .u64 t; cvta.to.shared.u64 t, %1; cvt.u32.u64 %0, t; }"
        : "=r"(a) : "l"(p));
    return a;
}
__device__ __forceinline__ void mbar_init(uint32_t mbar, uint32_t count) {
    asm volatile("mbarrier.init.shared.b64 [%0], %1;" :: "r"(mbar), "r"(count) : "memory");
}
__device__ __forceinline__ void mbar_expect_tx(uint32_t mbar, uint32_t bytes) {
    asm volatile("mbarrier.arrive.expect_tx.shared.b64 _, [%0], %1;"
                 :: "r"(mbar), "r"(bytes) : "memory");
}
__device__ __forceinline__ void bulk_g2s(uint32_t sdst, const void* gsrc,
                                         uint32_t bytes, uint32_t mbar) {
    asm volatile("cp.async.bulk.shared::cta.global.mbarrier::complete_tx::bytes "
                 "[%0], [%1], %2, [%3];"
                 :: "r"(sdst), "l"(gsrc), "r"(bytes), "r"(mbar) : "memory");
}
__device__ __forceinline__ void mbar_wait(uint32_t mbar, uint32_t parity) {
    asm volatile(
        "{\n\t"
        ".reg .pred P;\n\t"
        "W%=:\n\t"
        "mbarrier.try_wait.parity.acquire.cta.shared::cta.b64 P, [%0], %1, 0x989680;\n\t"
        "@P bra D%=;\n\t"
        "bra W%=;\n\t"
        "D%=:\n\t"
        "}" :: "r"(mbar), "r"(parity) : "memory");
}

__global__ __launch_bounds__(NTHREADS)
void hinge_dualpipe_kernel(const char* __restrict__ logit_g,
                           const int2* __restrict__ label_g2,
                           const int2* __restrict__ repr_g2,
                           const float* __restrict__ logit_s,
                           const int* __restrict__ label_s,
                           const int* __restrict__ repr_s,
                           int ntiles, int Bmain, int B,
                           float* __restrict__ out)
{
    extern __shared__ __align__(16) char sbuf[];     // NSTAGES * LOG_BYTES
    __shared__ __align__(8) unsigned long long smbar[NSTAGES];
    __shared__ int stile[NSTAGES];

    const int t = threadIdx.x;
    const uint32_t mb_base = smem_u32(&smbar[0]);
    const uint32_t sb_base = smem_u32(sbuf);

    if (t == 0) {
        #pragma unroll
        for (int s = 0; s < NSTAGES; s++) mbar_init(mb_base + 8u * s, 1);
    }
    __syncthreads();

    float acc = 0.0f;
    int ph[NSTAGES] = {0, 0, 0, 0};

    // bulk-copy ONLY the logits of a tile into stage s
    auto issue = [&](int s, int tile) {
        const int base_row = tile * ROWS_TILE;
        const int rows = min(ROWS_TILE, Bmain - base_row);
        const uint32_t lb = (uint32_t)(rows * 28);
        const uint32_t mb = mb_base + 8u * s;
        mbar_expect_tx(mb, lb);
        bulk_g2s(sb_base + (uint32_t)s * LOG_BYTES,
                 logit_g + (size_t)base_row * 28, lb, mb);
    };

    // prologue: grab NSTAGES tiles from the global queue
    if (t == 0) {
        #pragma unroll
        for (int p = 0; p < NSTAGES; p++) {
            int tl = (int)atomicAdd(&g_tile, 1u);
            stile[p] = tl;
            if (tl < ntiles) issue(p, tl);
        }
    }
    __syncthreads();

    // register prefetch of repr/label for the FIRST tile
    int2 pr0, pr1, pr2, prl;
    {
        const int tile0 = stile[0];
        if (tile0 < ntiles) {
            const int base_row = tile0 * ROWS_TILE;
            const int rows = min(ROWS_TILE, Bmain - base_row);
            if (2 * t + 1 < rows) {
                const size_t rbase = ((size_t)base_row * 12 + 24u * t) >> 3;
                pr0 = __ldcs(repr_g2 + rbase + 0);
                pr1 = __ldcs(repr_g2 + rbase + 1);
                pr2 = __ldcs(repr_g2 + rbase + 2);
                prl = __ldcs(label_g2 + (((size_t)base_row * 4 + 8u * t) >> 3));
            }
        }
    }

    int stage = 0;
    for (;;) {
        const int tile = stile[stage];       // uniform across block
        if (tile >= ntiles) break;

        mbar_wait(mb_base + 8u * stage, ph[stage]);
        ph[stage] ^= 1;

        const char* bp = sbuf + stage * LOG_BYTES;
        const int rows = min(ROWS_TILE, Bmain - tile * ROWS_TILE);

        // thread t owns local rows 2t, 2t+1; repr/label already in registers
        if (2 * t + 1 < rows) {
            const float2* lp = reinterpret_cast<const float2*>(bp + 56 * t);
            float2 l[7];
            #pragma unroll
            for (int k = 0; k < 7; k++) l[k] = lp[k];
            const float* lf = reinterpret_cast<const float*>(l);

            const int rv[6] = {pr0.x, pr0.y, pr1.x, pr1.y, pr2.x, pr2.y};
            const int lbv[2] = {prl.x, prl.y};

            #pragma unroll
            for (int row = 0; row < 2; row++) {
                unsigned mask = (1u << rv[row * 3 + 0])
                              | (1u << rv[row * 3 + 1])
                              | (1u << rv[row * 3 + 2]);
                float tg = (lbv[row] == 1) ? 1.0f : 0.0f;
                #pragma unroll
                for (int jj = 0; jj < NUM_CLASSES; jj++) {
                    float d = lf[row * NUM_CLASSES + jj] - tg;
                    acc += ((mask >> jj) & 1u) ? fabsf(d) : fmaxf(d, 0.0f);
                }
            }
        }
        __syncthreads();   // stage fully consumed before refill

        // refill this slot from the global work queue (bulk logits only)
        if (t == 0) {
            int ftl = (int)atomicAdd(&g_tile, 1u);
            stile[stage] = ftl;
            if (ftl < ntiles) issue(stage, ftl);
        }

        // prefetch repr/label registers for the NEXT consumed tile
        // (stile[next] was written NSTAGES-1 iterations ago; barrier-separated)
        {
            const int nt = stile[(stage + 1) & (NSTAGES - 1)];
            if (nt < ntiles) {
                const int nbase = nt * ROWS_TILE;
                const int nrows = min(ROWS_TILE, Bmain - nbase);
                if (2 * t + 1 < nrows) {
                    const size_t rbase = ((size_t)nbase * 12 + 24u * t) >> 3;
                    pr0 = __ldcs(repr_g2 + rbase + 0);
                    pr1 = __ldcs(repr_g2 + rbase + 1);
                    pr2 = __ldcs(repr_g2 + rbase + 2);
                    prl = __ldcs(label_g2 + (((size_t)nbase * 4 + 8u * t) >> 3));
                }
            }
        }

        stage = (stage == NSTAGES - 1) ? 0 : stage + 1;
    }

    // remainder rows (B % 4 != 0), direct from gmem
    if (blockIdx.x == 0 && t == 0) {
        for (int row = Bmain; row < B; row++) {
            unsigned mask = (1u << repr_s[(size_t)row * 3 + 0])
                          | (1u << repr_s[(size_t)row * 3 + 1])
                          | (1u << repr_s[(size_t)row * 3 + 2]);
            float tg = (label_s[row] == 1) ? 1.0f : 0.0f;
            for (int jj = 0; jj < NUM_CLASSES; jj++) {
                float d = logit_s[(size_t)row * NUM_CLASSES + jj] - tg;
                acc += ((mask >> jj) & 1u) ? fabsf(d) : fmaxf(d, 0.0f);
            }
        }
    }

    // intra-block reduce
    #pragma unroll
    for (int o = 16; o > 0; o >>= 1)
        acc += __shfl_down_sync(0xffffffffu, acc, o);

    __shared__ float sred[NTHREADS / 32];
    if ((t & 31) == 0) sred[t >> 5] = acc;
    __syncthreads();

    // tiny epilogue: one f64 atomic per block + last-block scalar writeout
    if (t == 0) {
        float v = 0.0f;
        #pragma unroll
        for (int w = 0; w < NTHREADS / 32; w++) v += sred[w];

        atomicAdd(&g_sum, (double)v);
        __threadfence();
        unsigned int prev = atomicAdd(&g_done_count, 1u);
        if (prev == (unsigned)gridDim.x - 1u) {
            double total = atomicAdd(&g_sum, 0.0);
            *out = (float)total;
            g_sum = 0.0;
            g_done_count = 0u;
            g_tile = 0u;      // reset work queue for next graph replay
        }
    }
}

extern "C" void kernel_launch(void* const* d_in, const int* in_sizes, int n_in,
                              void* d_out, int out_size)
{
    // logit is [B,7] fp32 at d_in[0] (largest input, 7-multiple element count).
    const float* logit = (const float*)d_in[0];
    const int B = in_sizes[0] / NUM_CLASSES;

    // Disambiguate label ([B] int32) vs repr_num ([B,3] int32) by element count.
    const int* label;
    const int* repr;
    if (in_sizes[1] == B) {
        label = (const int*)d_in[1];
        repr  = (const int*)d_in[2];
    } else {
        label = (const int*)d_in[2];
        repr  = (const int*)d_in[1];
    }

    const int Bmain = (B / 4) * 4;
    const int ntiles = (Bmain + ROWS_TILE - 1) / ROWS_TILE;

    static bool attr_set = false;
    if (!attr_set) {
        cudaFuncSetAttribute(hinge_dualpipe_kernel,
                             cudaFuncAttributeMaxDynamicSharedMemorySize, SMEM_DYN);
        attr_set = true;
    }

    hinge_dualpipe_kernel<<<NBLOCKS, NTHREADS, SMEM_DYN>>>(
        (const char*)logit, (const int2*)label, (const int2*)repr,
        logit, label, repr, ntiles, Bmain, B, (float*)d_out);
}

// round 15
// speedup vs baseline: 1.0615x; 1.0615x over previous
#include <cuda_runtime.h>
#include <cstdint>

#define NUM_CLASSES 7
#define NCONS 256                      // consumer threads (rows 2t,2t+1)
#define NTHREADS 288                   // + 1 producer warp
#define ROWS_TILE 512
#define LOG_BYTES (ROWS_TILE * 28)     // 14336
#define REP_BYTES (ROWS_TILE * 12)     //  6144
#define LAB_BYTES (ROWS_TILE * 4)      //  2048
#define BUF_BYTES (LOG_BYTES + REP_BYTES + LAB_BYTES)  // 22528
#define NSTAGES 3
#define SMEM_DYN (NSTAGES * BUF_BYTES) // 67584 -> 3 blocks/SM
#define NBLOCKS 444

__device__ double g_sum = 0.0;
__device__ unsigned int g_done_count = 0;
__device__ unsigned int g_tile = 0;

__device__ __forceinline__ uint32_t smem_u32(const void* p) {
    uint32_t a;
    asm("{ .reg .u64 t; cvta.to.shared.u64 t, %1; cvt.u32.u64 %0, t; }"
        : "=r"(a) : "l"(p));
    return a;
}
__device__ __forceinline__ void mbar_init(uint32_t mbar, uint32_t count) {
    asm volatile("mbarrier.init.shared.b64 [%0], %1;" :: "r"(mbar), "r"(count) : "memory");
}
__device__ __forceinline__ void mbar_arrive(uint32_t mbar) {
    asm volatile("mbarrier.arrive.shared.b64 _, [%0];" :: "r"(mbar) : "memory");
}
__device__ __forceinline__ void mbar_expect_tx(uint32_t mbar, uint32_t bytes) {
    asm volatile("mbarrier.arrive.expect_tx.shared.b64 _, [%0], %1;"
                 :: "r"(mbar), "r"(bytes) : "memory");
}
__device__ __forceinline__ void bulk_g2s(uint32_t sdst, const void* gsrc,
                                         uint32_t bytes, uint32_t mbar) {
    asm volatile("cp.async.bulk.shared::cta.global.mbarrier::complete_tx::bytes "
                 "[%0], [%1], %2, [%3];"
                 :: "r"(sdst), "l"(gsrc), "r"(bytes), "r"(mbar) : "memory");
}
__device__ __forceinline__ void mbar_wait(uint32_t mbar, uint32_t parity) {
    asm volatile(
        "{\n\t"
        ".reg .pred P;\n\t"
        "W%=:\n\t"
        "mbarrier.try_wait.parity.acquire.cta.shared::cta.b64 P, [%0], %1, 0x989680;\n\t"
        "@P bra D%=;\n\t"
        "bra W%=;\n\t"
        "D%=:\n\t"
        "}" :: "r"(mbar), "r"(parity) : "memory");
}
__device__ __forceinline__ void fence_async_shared() {
    asm volatile("fence.proxy.async.shared::cta;" ::: "memory");
}

__global__ __launch_bounds__(NTHREADS)
void hinge_ws_kernel(const char* __restrict__ logit_g,
                     const char* __restrict__ label_g,
                     const char* __restrict__ repr_g,
                     const float* __restrict__ logit_s,
                     const int* __restrict__ label_s,
                     const int* __restrict__ repr_s,
                     int ntiles, int Bmain, int B,
                     float* __restrict__ out)
{
    extern __shared__ __align__(16) char sbuf[];        // NSTAGES * BUF_BYTES
    __shared__ __align__(8) unsigned long long sfull[NSTAGES];
    __shared__ __align__(8) unsigned long long sempty[NSTAGES];
    __shared__ int stile[NSTAGES];

    const int t = threadIdx.x;
    const uint32_t fb = smem_u32(&sfull[0]);
    const uint32_t eb = smem_u32(&sempty[0]);
    const uint32_t sb_base = smem_u32(sbuf);

    if (t == 0) {
        #pragma unroll
        for (int s = 0; s < NSTAGES; s++) {
            mbar_init(fb + 8u * s, 1);       // flipped by TMA tx or sentinel arrive
            mbar_init(eb + 8u * s, NCONS);   // flipped when all consumers done
        }
    }
    __syncthreads();   // only block-wide barrier (after init)

    float acc = 0.0f;

    if (t >= NCONS) {
        // ───────── producer warp (warp 8); lane 0 does the work ─────────
        const int lane = t - NCONS;
        int phe[NSTAGES] = {0, 0, 0};
        bool active[NSTAGES] = {false, false, false};
        int nsent = 0;

        auto issue = [&](int s, int tile) {
            const int base_row = tile * ROWS_TILE;
            const int rows = min(ROWS_TILE, Bmain - base_row);
            const uint32_t lb = (uint32_t)(rows * 28);
            const uint32_t rb = (uint32_t)(rows * 12);
            const uint32_t bb = (uint32_t)(rows * 4);
            const uint32_t mb = fb + 8u * s;
            const uint32_t sb = sb_base + (uint32_t)s * BUF_BYTES;
            mbar_expect_tx(mb, lb + rb + bb);
            bulk_g2s(sb,                        logit_g + (size_t)base_row * 28, lb, mb);
            bulk_g2s(sb + LOG_BYTES,            repr_g  + (size_t)base_row * 12, rb, mb);
            bulk_g2s(sb + LOG_BYTES + REP_BYTES, label_g + (size_t)base_row * 4, bb, mb);
        };

        // prologue: fill all stages
        #pragma unroll
        for (int p = 0; p < NSTAGES; p++) {
            int tl;
            if (lane == 0) tl = (int)atomicAdd(&g_tile, 1u);
            tl = __shfl_sync(0xffffffffu, tl, 0);
            if (lane == 0) {
                stile[p] = tl;
                fence_async_shared();          // order stile write before async ops
                if (tl < ntiles) issue(p, tl);
                else             mbar_arrive(fb + 8u * p);   // sentinel flip
            }
            active[p] = (tl < ntiles);
            if (!active[p]) nsent++;
        }

        int s = 0;
        while (nsent < NSTAGES) {
            if (active[s]) {
                mbar_wait(eb + 8u * s, phe[s]);   // all lanes spin (same barrier)
                phe[s] ^= 1;
                int tl;
                if (lane == 0) tl = (int)atomicAdd(&g_tile, 1u);
                tl = __shfl_sync(0xffffffffu, tl, 0);
                if (lane == 0) {
                    stile[s] = tl;
                    fence_async_shared();
                    if (tl < ntiles) issue(s, tl);
                    else             mbar_arrive(fb + 8u * s);
                }
                if (tl >= ntiles) { active[s] = false; nsent++; }
            }
            s = (s + 1 == NSTAGES) ? 0 : s + 1;
        }
    } else {
        // ───────── consumers: 256 threads, rows 2t/2t+1 per tile ─────────
        int phf[NSTAGES] = {0, 0, 0};
        int s = 0;
        for (;;) {
            mbar_wait(fb + 8u * s, phf[s]);
            phf[s] ^= 1;

            const int tile = stile[s];          // valid: acquire after full-flip
            if (tile >= ntiles) break;

            const char* bp = sbuf + s * BUF_BYTES;
            const int rows = min(ROWS_TILE, Bmain - tile * ROWS_TILE);

            if (2 * t + 1 < rows) {
                const float2* lp = reinterpret_cast<const float2*>(bp + 56 * t);
                float2 l[7];
                #pragma unroll
                for (int k = 0; k < 7; k++) l[k] = lp[k];
                const float* lf = reinterpret_cast<const float*>(l);

                const int2* rp = reinterpret_cast<const int2*>(bp + LOG_BYTES + 24 * t);
                int2 r[3];
                #pragma unroll
                for (int k = 0; k < 3; k++) r[k] = rp[k];
                const int* rv = reinterpret_cast<const int*>(r);

                int2 lab = *reinterpret_cast<const int2*>(bp + LOG_BYTES + REP_BYTES + 8 * t);
                const int* lbv = reinterpret_cast<const int*>(&lab);

                #pragma unroll
                for (int row = 0; row < 2; row++) {
                    unsigned mask = (1u << rv[row * 3 + 0])
                                  | (1u << rv[row * 3 + 1])
                                  | (1u << rv[row * 3 + 2]);
                    float tg = (lbv[row] == 1) ? 1.0f : 0.0f;
                    #pragma unroll
                    for (int jj = 0; jj < NUM_CLASSES; jj++) {
                        float d = lf[row * NUM_CLASSES + jj] - tg;
                        acc += ((mask >> jj) & 1u) ? fabsf(d) : fmaxf(d, 0.0f);
                    }
                }
            }
            mbar_arrive(eb + 8u * s);           // this thread done with stage s
            s = (s + 1 == NSTAGES) ? 0 : s + 1;
        }

        // remainder rows (B % 4 != 0), direct from gmem
        if (blockIdx.x == 0 && t == 0) {
            for (int row = Bmain; row < B; row++) {
                unsigned mask = (1u << repr_s[(size_t)row * 3 + 0])
                              | (1u << repr_s[(size_t)row * 3 + 1])
                              | (1u << repr_s[(size_t)row * 3 + 2]);
                float tg = (label_s[row] == 1) ? 1.0f : 0.0f;
                for (int jj = 0; jj < NUM_CLASSES; jj++) {
                    float d = logit_s[(size_t)row * NUM_CLASSES + jj] - tg;
                    acc += ((mask >> jj) & 1u) ? fabsf(d) : fmaxf(d, 0.0f);
                }
            }
        }
    }

    // block reduce (9 warps; producer warp contributes 0)
    #pragma unroll
    for (int o = 16; o > 0; o >>= 1)
        acc += __shfl_down_sync(0xffffffffu, acc, o);

    __shared__ float sred[NTHREADS / 32];
    if ((t & 31) == 0) sred[t >> 5] = acc;
    __syncthreads();

    if (t == 0) {
        float v = 0.0f;
        #pragma unroll
        for (int w = 0; w < NTHREADS / 32; w++) v += sred[w];

        atomicAdd(&g_sum, (double)v);
        __threadfence();
        unsigned int prev = atomicAdd(&g_done_count, 1u);
        if (prev == (unsigned)gridDim.x - 1u) {
            double total = atomicAdd(&g_sum, 0.0);
            *out = (float)total;
            g_sum = 0.0;
            g_done_count = 0u;
            g_tile = 0u;
        }
    }
}

extern "C" void kernel_launch(void* const* d_in, const int* in_sizes, int n_in,
                              void* d_out, int out_size)
{
    const float* logit = (const float*)d_in[0];
    const int B = in_sizes[0] / NUM_CLASSES;

    const int* label;
    const int* repr;
    if (in_sizes[1] == B) {
        label = (const int*)d_in[1];
        repr  = (const int*)d_in[2];
    } else {
        label = (const int*)d_in[2];
        repr  = (const int*)d_in[1];
    }

    const int Bmain = (B / 4) * 4;
    const int ntiles = (Bmain + ROWS_TILE - 1) / ROWS_TILE;

    static bool attr_set = false;
    if (!attr_set) {
        cudaFuncSetAttribute(hinge_ws_kernel,
                             cudaFuncAttributeMaxDynamicSharedMemorySize, SMEM_DYN);
        attr_set = true;
    }

    hinge_ws_kernel<<<NBLOCKS, NTHREADS, SMEM_DYN>>>(
        (const char*)logit, (const char*)label, (const char*)repr,
        logit, label, repr, ntiles, Bmain, B, (float*)d_out);
}

// round 16
// speedup vs baseline: 1.0845x; 1.0216x over previous
#include <cuda_runtime.h>
#include <cstdint>

#define NUM_CLASSES 7
#define NTHREADS 512
#define ROWS_TILE 1024                // rows per tile (multiple of 4)
#define LOG_BYTES (ROWS_TILE * 28)    // 28672
#define REP_BYTES (ROWS_TILE * 12)    // 12288
#define LAB_BYTES (ROWS_TILE * 4)     //  4096
#define BUF_BYTES (LOG_BYTES + REP_BYTES + LAB_BYTES)  // 45056
#define NSTAGES 2
#define SMEM_DYN (NSTAGES * BUF_BYTES)   // 90112 -> 2 blocks/SM
#define NBLOCKS 296                      // 148 SMs * 2 resident

__device__ double g_sum = 0.0;
__device__ unsigned int g_done_count = 0;
__device__ unsigned int g_tile = 0;

__device__ __forceinline__ uint32_t smem_u32(const void* p) {
    uint32_t a;
    asm("{ .reg .u64 t; cvta.to.shared.u64 t, %1; cvt.u32.u64 %0, t; }"
        : "=r"(a) : "l"(p));
    return a;
}
__device__ __forceinline__ void mbar_init(uint32_t mbar, uint32_t count) {
    asm volatile("mbarrier.init.shared.b64 [%0], %1;" :: "r"(mbar), "r"(count) : "memory");
}
__device__ __forceinline__ void mbar_expect_tx(uint32_t mbar, uint32_t bytes) {
    asm volatile("mbarrier.arrive.expect_tx.shared.b64 _, [%0], %1;"
                 :: "r"(mbar), "r"(bytes) : "memory");
}
__device__ __forceinline__ void bulk_g2s(uint32_t sdst, const void* gsrc,
                                         uint32_t bytes, uint32_t mbar) {
    asm volatile("cp.async.bulk.shared::cta.global.mbarrier::complete_tx::bytes "
                 "[%0], [%1], %2, [%3];"
                 :: "r"(sdst), "l"(gsrc), "r"(bytes), "r"(mbar) : "memory");
}
__device__ __forceinline__ void mbar_wait(uint32_t mbar, uint32_t parity) {
    asm volatile(
        "{\n\t"
        ".reg .pred P;\n\t"
        "W%=:\n\t"
        "mbarrier.try_wait.parity.acquire.cta.shared::cta.b64 P, [%0], %1, 0x989680;\n\t"
        "@P bra D%=;\n\t"
        "bra W%=;\n\t"
        "D%=:\n\t"
        "}" :: "r"(mbar), "r"(parity) : "memory");
}

__global__ __launch_bounds__(NTHREADS)
void hinge_big_kernel(const char* __restrict__ logit_g,
                      const char* __restrict__ label_g,
                      const char* __restrict__ repr_g,
                      const float* __restrict__ logit_s,
                      const int* __restrict__ label_s,
                      const int* __restrict__ repr_s,
                      int ntiles, int Bmain, int B,
                      float* __restrict__ out)
{
    extern __shared__ __align__(16) char sbuf[];     // NSTAGES * BUF_BYTES
    __shared__ __align__(8) unsigned long long smbar[NSTAGES];
    __shared__ int stile[NSTAGES];

    const int t = threadIdx.x;
    const uint32_t mb_base = smem_u32(&smbar[0]);
    const uint32_t sb_base = smem_u32(sbuf);

    if (t == 0) {
        #pragma unroll
        for (int s = 0; s < NSTAGES; s++) mbar_init(mb_base + 8u * s, 1);
    }
    __syncthreads();

    float acc = 0.0f;
    int ph[NSTAGES] = {0, 0};

    auto issue = [&](int s, int tile) {
        const int base_row = tile * ROWS_TILE;
        const int rows = min(ROWS_TILE, Bmain - base_row);
        const uint32_t lb = (uint32_t)(rows * 28);
        const uint32_t rb = (uint32_t)(rows * 12);
        const uint32_t bb = (uint32_t)(rows * 4);
        const uint32_t mb = mb_base + 8u * s;
        const uint32_t sb = sb_base + (uint32_t)s * BUF_BYTES;
        mbar_expect_tx(mb, lb + rb + bb);
        bulk_g2s(sb,                         logit_g + (size_t)base_row * 28, lb, mb);
        bulk_g2s(sb + LOG_BYTES,             repr_g  + (size_t)base_row * 12, rb, mb);
        bulk_g2s(sb + LOG_BYTES + REP_BYTES, label_g + (size_t)base_row * 4,  bb, mb);
    };

    // prologue: grab NSTAGES tiles from the global queue
    if (t == 0) {
        #pragma unroll
        for (int p = 0; p < NSTAGES; p++) {
            int tl = (int)atomicAdd(&g_tile, 1u);
            stile[p] = tl;
            if (tl < ntiles) issue(p, tl);
        }
    }
    __syncthreads();

    int stage = 0;
    for (;;) {
        const int tile = stile[stage];       // uniform across block
        if (tile >= ntiles) break;

        mbar_wait(mb_base + 8u * stage, ph[stage]);
        ph[stage] ^= 1;

        const char* bp = sbuf + stage * BUF_BYTES;
        const int rows = min(ROWS_TILE, Bmain - tile * ROWS_TILE);

        // thread t owns local rows 2t, 2t+1 (rows is a multiple of 4)
        if (2 * t + 1 < rows) {
            const float2* lp = reinterpret_cast<const float2*>(bp + 56 * t);
            float2 l[7];
            #pragma unroll
            for (int k = 0; k < 7; k++) l[k] = lp[k];
            const float* lf = reinterpret_cast<const float*>(l);

            const int2* rp = reinterpret_cast<const int2*>(bp + LOG_BYTES + 24 * t);
            int2 r[3];
            #pragma unroll
            for (int k = 0; k < 3; k++) r[k] = rp[k];
            const int* rv = reinterpret_cast<const int*>(r);

            int2 lab = *reinterpret_cast<const int2*>(bp + LOG_BYTES + REP_BYTES + 8 * t);
            const int* lbv = reinterpret_cast<const int*>(&lab);

            #pragma unroll
            for (int row = 0; row < 2; row++) {
                unsigned mask = (1u << rv[row * 3 + 0])
                              | (1u << rv[row * 3 + 1])
                              | (1u << rv[row * 3 + 2]);
                float tg = (lbv[row] == 1) ? 1.0f : 0.0f;
                #pragma unroll
                for (int jj = 0; jj < NUM_CLASSES; jj++) {
                    float d = lf[row * NUM_CLASSES + jj] - tg;
                    acc += ((mask >> jj) & 1u) ? fabsf(d) : fmaxf(d, 0.0f);
                }
            }
        }
        __syncthreads();   // stage fully consumed before refill

        // refill this slot from the global work queue
        if (t == 0) {
            int ftl = (int)atomicAdd(&g_tile, 1u);
            stile[stage] = ftl;
            if (ftl < ntiles) issue(stage, ftl);
        }
        // next read of stile[stage] is one full iteration (with barrier) away

        stage ^= 1;
    }

    // remainder rows (B % 4 != 0), direct from gmem
    if (blockIdx.x == 0 && t == 0) {
        for (int row = Bmain; row < B; row++) {
            unsigned mask = (1u << repr_s[(size_t)row * 3 + 0])
                          | (1u << repr_s[(size_t)row * 3 + 1])
                          | (1u << repr_s[(size_t)row * 3 + 2]);
            float tg = (label_s[row] == 1) ? 1.0f : 0.0f;
            for (int jj = 0; jj < NUM_CLASSES; jj++) {
                float d = logit_s[(size_t)row * NUM_CLASSES + jj] - tg;
                acc += ((mask >> jj) & 1u) ? fabsf(d) : fmaxf(d, 0.0f);
            }
        }
    }

    // intra-block reduce
    #pragma unroll
    for (int o = 16; o > 0; o >>= 1)
        acc += __shfl_down_sync(0xffffffffu, acc, o);

    __shared__ float sred[NTHREADS / 32];
    if ((t & 31) == 0) sred[t >> 5] = acc;
    __syncthreads();

    // tiny epilogue: one f64 atomic per block + last-block scalar writeout
    if (t == 0) {
        float v = 0.0f;
        #pragma unroll
        for (int w = 0; w < NTHREADS / 32; w++) v += sred[w];

        atomicAdd(&g_sum, (double)v);
        __threadfence();
        unsigned int prev = atomicAdd(&g_done_count, 1u);
        if (prev == (unsigned)gridDim.x - 1u) {
            double total = atomicAdd(&g_sum, 0.0);
            *out = (float)total;
            g_sum = 0.0;
            g_done_count = 0u;
            g_tile = 0u;      // reset work queue for next graph replay
        }
    }
}

extern "C" void kernel_launch(void* const* d_in, const int* in_sizes, int n_in,
                              void* d_out, int out_size)
{
    // logit is [B,7] fp32 at d_in[0] (largest input, 7-multiple element count).
    const float* logit = (const float*)d_in[0];
    const int B = in_sizes[0] / NUM_CLASSES;

    // Disambiguate label ([B] int32) vs repr_num ([B,3] int32) by element count.
    const int* label;
    const int* repr;
    if (in_sizes[1] == B) {
        label = (const int*)d_in[1];
        repr  = (const int*)d_in[2];
    } else {
        label = (const int*)d_in[2];
        repr  = (const int*)d_in[1];
    }

    const int Bmain = (B / 4) * 4;
    const int ntiles = (Bmain + ROWS_TILE - 1) / ROWS_TILE;

    static bool attr_set = false;
    if (!attr_set) {
        cudaFuncSetAttribute(hinge_big_kernel,
                             cudaFuncAttributeMaxDynamicSharedMemorySize, SMEM_DYN);
        attr_set = true;
    }

    hinge_big_kernel<<<NBLOCKS, NTHREADS, SMEM_DYN>>>(
        (const char*)logit, (const char*)label, (const char*)repr,
        logit, label, repr, ntiles, Bmain, B, (float*)d_out);
}